// round 13
// baseline (speedup 1.0000x reference)
#include <cuda_runtime.h>
#include <cuda_bf16.h>
#include <cstdint>

// EdgeConvE: out[v,h] = sum_w A[v,w] * relu(S[v,h] + T[w,h] + sum_e E[v,w,e]*We[e,h])
// N=1024, F=32, E_ATTR=8, H=OUT 64.
// R12 = R8 baseline + ONE structural change: 2 v per warp sharing each Tf
// fragment (C-operand reused by two MMAs), S applied in epilogue.
// Halves Tf L1 traffic; w-split widened to quarters to keep grid=256 (one wave).
//   prep_st  = R5/R7 version              ~5 us
//   edge_main = paired-v loop             (16.3 -> ~12-13 us predicted)
//   combine  = 4-way deterministic sum    ~2.5 us

#define N_NODES 1024
#define F_NODE  32
#define E_ATTR  8
#define H_OUT   64

__device__ __forceinline__ uint32_t to_tf32(float f) {
    uint32_t u; asm("cvt.rna.tf32.f32 %0, %1;" : "=r"(u) : "f"(f)); return u;
}

// ---------- scratch ----------
__device__ float  g_S [N_NODES * H_OUT];             // 256 KB: S[v,h]=X@(Ws-Wd)+b
__device__ float4 g_Tf[(N_NODES / 16) * 8 * 32];     // 256 KB: T in MMA-C frag layout
__device__ float  g_part[4][N_NODES * H_OUT];        // 1 MB: per-quarter partials

// ---------- kernel 1: S + fragged T ----------
// grid 256, block 256: 4 v per block, one (vl,h) per thread.
__global__ void __launch_bounds__(256)
prep_st(const float* __restrict__ X, const float* __restrict__ W,
        const float* __restrict__ b) {
    __shared__ float ws[2 * F_NODE * H_OUT];   // 16 KB (rows 0..63 of W)
    __shared__ float xs[4][F_NODE];
    const int tid = threadIdx.x;
    const int v0  = blockIdx.x * 4;

    const float4* W4 = reinterpret_cast<const float4*>(W);
    float4* ws4 = reinterpret_cast<float4*>(ws);
#pragma unroll
    for (int i = 0; i < 4; i++) ws4[tid + 256 * i] = W4[tid + 256 * i];
    if (tid < 32)
        reinterpret_cast<float4*>(xs)[tid] =
            reinterpret_cast<const float4*>(X + v0 * F_NODE)[tid];
    __syncthreads();

    const int h  = tid & 63;
    const int vl = tid >> 6;
    float s = __ldg(&b[h]), t = 0.0f;
#pragma unroll
    for (int f = 0; f < F_NODE; f++) {
        float x  = xs[vl][f];
        float wv = ws[f * H_OUT + h];
        float wd = ws[(f + F_NODE) * H_OUT + h];
        s = fmaf(x, wv - wd, s);
        t = fmaf(x, wd, t);
    }
    const int v = v0 + vl;
    g_S[v * H_OUT + h] = s;
    // scatter T into MMA-C frag layout (matches main kernel's read mapping):
    const int wt   = v >> 4;
    const int gid  = v & 7;
    const int rs   = (v >> 3) & 1;
    const int t4   = (h >> 1) & 3;
    const int j    = h >> 3;
    const int elem = (h & 1) + 2 * rs;
    reinterpret_cast<float*>(g_Tf)[(((wt * 8 + j) * 32) + gid * 4 + t4) * 4 + elem] = t;
}

// ---------- kernel 2: main (paired-v: 2 v per warp share Tf fragments) ----------
// Block: 8 warps = 16 v, all scanning the SAME w-quarter (16 wt).
// Grid: (1024/16) * 4 quarters = 256 blocks, 2 CTA/SM, one wave.
// K-permutation (A & B consistent): k-slot t4 <-> attr 2t4, slot t4+4 <-> attr 2t4+1.
// Tf frag is MMA C-operand for BOTH v's; S added in epilogue before relu.
__global__ void __launch_bounds__(256, 2)
edge_main(const float* __restrict__ E, const int* __restrict__ A,
          const float* __restrict__ W) {
    const int vg   = blockIdx.x >> 2;      // 0..63
    const int q    = blockIdx.x & 3;       // w-quarter
    const int warp = threadIdx.x >> 5;
    const int lane = threadIdx.x & 31;
    const int gid  = lane >> 2;            // 0..7
    const int t4   = lane & 3;             // 0..3
    const int va   = vg * 16 + warp * 2;   // first v of the pair
    const int vb   = va + 1;

    // B frags (We in tf32), permuted-K rows 2t4 and 2t4+1 (shared by both v)
    uint32_t bf0[8], bf1[8];
#pragma unroll
    for (int j = 0; j < 8; j++) {
        bf0[j] = to_tf32(W[(2 * F_NODE + 2 * t4)     * H_OUT + j * 8 + gid]);
        bf1[j] = to_tf32(W[(2 * F_NODE + 2 * t4 + 1) * H_OUT + j * 8 + gid]);
    }
    // S pairs for each v
    float2 sa[8], sb[8];
#pragma unroll
    for (int j = 0; j < 8; j++) {
        sa[j] = *(const float2*)&g_S[va * H_OUT + j * 8 + 2 * t4];
        sb[j] = *(const float2*)&g_S[vb * H_OUT + j * 8 + 2 * t4];
    }

    float accA0[8], accA1[8], accB0[8], accB1[8];
#pragma unroll
    for (int j = 0; j < 8; j++) {
        accA0[j] = 0.0f; accA1[j] = 0.0f;
        accB0[j] = 0.0f; accB1[j] = 0.0f;
    }

    const float* __restrict__ Ea = E + (size_t)va * (N_NODES * E_ATTR);
    const float* __restrict__ Eb = E + (size_t)vb * (N_NODES * E_ATTR);
    const int*   __restrict__ Aa = A + va * N_NODES;
    const int*   __restrict__ Ab = A + vb * N_NODES;
    const float4* __restrict__ Tf = g_Tf;

    const int wt0 = q * 16;
#pragma unroll 2
    for (int wt = wt0; wt < wt0 + 16; wt++) {
        const int r0 = wt * 16 + gid;
        const int r1 = r0 + 8;
        // E A-frags for both v (permuted K: contiguous LDG.64 per row)
        float2 ea0 = *(const float2*)&Ea[r0 * E_ATTR + 2 * t4];
        float2 ea1 = *(const float2*)&Ea[r1 * E_ATTR + 2 * t4];
        float2 eb0 = *(const float2*)&Eb[r0 * E_ATTR + 2 * t4];
        float2 eb1 = *(const float2*)&Eb[r1 * E_ATTR + 2 * t4];
        uint32_t aa0 = to_tf32(ea0.x), aa2 = to_tf32(ea0.y);
        uint32_t aa1 = to_tf32(ea1.x), aa3 = to_tf32(ea1.y);
        uint32_t ab0 = to_tf32(eb0.x), ab2 = to_tf32(eb0.y);
        uint32_t ab1 = to_tf32(eb1.x), ab3 = to_tf32(eb1.y);
        float aFa0 = (float)Aa[r0], aFa1 = (float)Aa[r1];
        float aFb0 = (float)Ab[r0], aFb1 = (float)Ab[r1];
#pragma unroll
        for (int j = 0; j < 8; j++) {
            float4 c = Tf[(wt * 8 + j) * 32 + lane];   // ONE load, TWO MMAs
            float d0, d1, d2, d3;
            // v = va:  d = Ea @ We + Tf
            asm("mma.sync.aligned.m16n8k8.row.col.f32.tf32.tf32.f32 "
                "{%0,%1,%2,%3}, {%4,%5,%6,%7}, {%8,%9}, {%10,%11,%12,%13};"
                : "=f"(d0), "=f"(d1), "=f"(d2), "=f"(d3)
                : "r"(aa0), "r"(aa1), "r"(aa2), "r"(aa3),
                  "r"(bf0[j]), "r"(bf1[j]),
                  "f"(c.x), "f"(c.y), "f"(c.z), "f"(c.w));
            float r0a = fmaxf(d0 + sa[j].x, 0.0f);
            float r1a = fmaxf(d1 + sa[j].y, 0.0f);
            float r2a = fmaxf(d2 + sa[j].x, 0.0f);
            float r3a = fmaxf(d3 + sa[j].y, 0.0f);
            accA0[j] = fmaf(aFa0, r0a, accA0[j]);
            accA0[j] = fmaf(aFa1, r2a, accA0[j]);
            accA1[j] = fmaf(aFa0, r1a, accA1[j]);
            accA1[j] = fmaf(aFa1, r3a, accA1[j]);
            // v = vb:  d = Eb @ We + Tf  (same c registers)
            asm("mma.sync.aligned.m16n8k8.row.col.f32.tf32.tf32.f32 "
                "{%0,%1,%2,%3}, {%4,%5,%6,%7}, {%8,%9}, {%10,%11,%12,%13};"
                : "=f"(d0), "=f"(d1), "=f"(d2), "=f"(d3)
                : "r"(ab0), "r"(ab1), "r"(ab2), "r"(ab3),
                  "r"(bf0[j]), "r"(bf1[j]),
                  "f"(c.x), "f"(c.y), "f"(c.z), "f"(c.w));
            float r0b = fmaxf(d0 + sb[j].x, 0.0f);
            float r1b = fmaxf(d1 + sb[j].y, 0.0f);
            float r2b = fmaxf(d2 + sb[j].x, 0.0f);
            float r3b = fmaxf(d3 + sb[j].y, 0.0f);
            accB0[j] = fmaf(aFb0, r0b, accB0[j]);
            accB0[j] = fmaf(aFb1, r2b, accB0[j]);
            accB1[j] = fmaf(aFb0, r1b, accB1[j]);
            accB1[j] = fmaf(aFb1, r3b, accB1[j]);
        }
    }

    // reduce across the 8 row-groups (xor over gid bits: lanes 4,8,16)
#pragma unroll
    for (int j = 0; j < 8; j++) {
        float x0 = accA0[j], x1 = accA1[j], y0 = accB0[j], y1 = accB1[j];
        x0 += __shfl_xor_sync(0xffffffffu, x0, 4);
        x1 += __shfl_xor_sync(0xffffffffu, x1, 4);
        y0 += __shfl_xor_sync(0xffffffffu, y0, 4);
        y1 += __shfl_xor_sync(0xffffffffu, y1, 4);
        x0 += __shfl_xor_sync(0xffffffffu, x0, 8);
        x1 += __shfl_xor_sync(0xffffffffu, x1, 8);
        y0 += __shfl_xor_sync(0xffffffffu, y0, 8);
        y1 += __shfl_xor_sync(0xffffffffu, y1, 8);
        x0 += __shfl_xor_sync(0xffffffffu, x0, 16);
        x1 += __shfl_xor_sync(0xffffffffu, x1, 16);
        y0 += __shfl_xor_sync(0xffffffffu, y0, 16);
        y1 += __shfl_xor_sync(0xffffffffu, y1, 16);
        if (gid == 0) {
            *(float2*)&g_part[q][va * H_OUT + j * 8 + 2 * t4] = make_float2(x0, x1);
            *(float2*)&g_part[q][vb * H_OUT + j * 8 + 2 * t4] = make_float2(y0, y1);
        }
    }
}

// ---------- kernel 3: deterministic combine ----------
__global__ void combine(float* __restrict__ out) {
    const int i = blockIdx.x * 256 + threadIdx.x;
    out[i] = (g_part[0][i] + g_part[1][i]) + (g_part[2][i] + g_part[3][i]);
}

// ---------- launch ----------
extern "C" void kernel_launch(void* const* d_in, const int* in_sizes, int n_in,
                              void* d_out, int out_size) {
    const int*   adj = (const int*)d_in[0];       // (1,1024,1024) int32
    const float* X   = (const float*)d_in[1];     // (1,1024,32)
    const float* E   = (const float*)d_in[2];     // (1,1024,1024,8)
    const float* W   = (const float*)d_in[3];     // (72,64)
    const float* b   = (const float*)d_in[4];     // (64,)
    float* out = (float*)d_out;                   // (1,1024,64)

    prep_st<<<N_NODES / 4, 256>>>(X, W, b);
    edge_main<<<(N_NODES / 16) * 4, 256>>>(E, adj, W);
    combine<<<(N_NODES * H_OUT) / 256, 256>>>(out);
}